// round 2
// baseline (speedup 1.0000x reference)
#include <cuda_runtime.h>
#include <cstdint>

#define BB 4
#define TT 1024
#define DEMB 1024
#define NH 16
#define DH 64
#define LL 1344   // 21 * 64

// Scratch: K and V in (b, h, t, d) layout. __device__ globals (no runtime alloc).
__device__ float g_K[BB * NH * TT * DH];
__device__ float g_V[BB * NH * TT * DH];

// ---------------------------------------------------------------------------
// Projection: out[m][n] = sum_k x[m][k] * w[n][k] + bias[n]
// m = b*T + t (4096), n = h*64 + d (1024), scattered into g_K / g_V.
// blockIdx.z selects K (0) vs V (1).
// ---------------------------------------------------------------------------
__global__ __launch_bounds__(256, 4)
void proj_kernel(const float* __restrict__ x,
                 const float* __restrict__ wk, const float* __restrict__ bk,
                 const float* __restrict__ wv, const float* __restrict__ bv)
{
    const int which = blockIdx.z;
    const float* __restrict__ w    = which ? wv : wk;
    const float* __restrict__ bias = which ? bv : bk;
    float* __restrict__ out        = which ? g_V : g_K;

    __shared__ float As[16][65];   // [k][m]
    __shared__ float Bs[16][65];   // [k][n]

    const int m0 = blockIdx.y * 64;
    const int n0 = blockIdx.x * 64;
    const int tid = threadIdx.x;
    const int tx = tid & 15, ty = tid >> 4;

    float acc[4][4] = {};

    const int r  = tid >> 2;   // 0..63
    const int c4 = tid & 3;    // 0..3  (k group of 4)

    for (int k0 = 0; k0 < DEMB; k0 += 16) {
        {
            float4 av = *(const float4*)&x[(size_t)(m0 + r) * DEMB + k0 + c4 * 4];
            As[c4*4+0][r] = av.x; As[c4*4+1][r] = av.y;
            As[c4*4+2][r] = av.z; As[c4*4+3][r] = av.w;
            float4 bv4 = *(const float4*)&w[(size_t)(n0 + r) * DEMB + k0 + c4 * 4];
            Bs[c4*4+0][r] = bv4.x; Bs[c4*4+1][r] = bv4.y;
            Bs[c4*4+2][r] = bv4.z; Bs[c4*4+3][r] = bv4.w;
        }
        __syncthreads();
        #pragma unroll
        for (int k = 0; k < 16; k++) {
            float a[4], b[4];
            #pragma unroll
            for (int i = 0; i < 4; i++) a[i] = As[k][ty*4 + i];
            #pragma unroll
            for (int j = 0; j < 4; j++) b[j] = Bs[k][tx*4 + j];
            #pragma unroll
            for (int i = 0; i < 4; i++)
                #pragma unroll
                for (int j = 0; j < 4; j++) acc[i][j] += a[i] * b[j];
        }
        __syncthreads();
    }

    #pragma unroll
    for (int i = 0; i < 4; i++) {
        const int m = m0 + ty*4 + i;
        const int b_ = m >> 10;       // batch
        const int t  = m & 1023;
        #pragma unroll
        for (int j = 0; j < 4; j++) {
            const int n = n0 + tx*4 + j;
            const int h = n >> 6;
            const int d = n & 63;
            out[(((size_t)(b_ * NH + h)) * TT + t) * DH + d] = acc[i][j] + bias[n];
        }
    }
}

// ---------------------------------------------------------------------------
// Flash-style masked attention.
// Block = (lt, h, b). 64 latent rows x full T=1024 streamed in 64-wide tiles.
// Mask is int32 (bool upcast by the harness): nonzero = keep.
// ---------------------------------------------------------------------------
#define SM_STRIDE 65
#define SMEM_ATTN ((4 * 64 * SM_STRIDE + 3 * 64) * sizeof(float))

__global__ __launch_bounds__(256)
void attn_kernel(const float* __restrict__ latq,
                 const int* __restrict__ mask,
                 float* __restrict__ out)
{
    extern __shared__ float smem[];
    float* lq_s = smem;                       // [d][l]  64 x 65
    float* k_s  = lq_s + 64 * SM_STRIDE;      // [d][t]
    float* v_s  = k_s  + 64 * SM_STRIDE;      // [t][d]
    float* s_s  = v_s  + 64 * SM_STRIDE;      // [l][t]
    float* m_s  = s_s  + 64 * SM_STRIDE;      // [64]
    float* l_s  = m_s + 64;
    float* c_s  = l_s + 64;

    const int lt = blockIdx.x, h = blockIdx.y, b = blockIdx.z;
    const int tid = threadIdx.x;
    const int tx = tid & 15, ty = tid >> 4;

    const float* __restrict__ lq = latq + (size_t)h * (LL * DH) + (size_t)(lt * 64) * DH;
    const float* __restrict__ Kp = g_K + ((size_t)(b * NH + h)) * TT * DH;
    const float* __restrict__ Vp = g_V + ((size_t)(b * NH + h)) * TT * DH;
    const int* __restrict__ mk = mask + ((size_t)b * LL + lt * 64) * TT;

    // load lq (scaled by H^-0.5 = 0.25), transposed to [d][l]
    #pragma unroll
    for (int i = 0; i < 16; i++) {
        const int e = tid + i * 256;
        const int l = e >> 6, d = e & 63;
        lq_s[d * SM_STRIDE + l] = lq[l * DH + d] * 0.25f;
    }
    if (tid < 64) { m_s[tid] = -1e9f; l_s[tid] = 0.f; }

    float O[4][4] = {};
    const int row = tid >> 2, sub = tid & 3;

    for (int t0 = 0; t0 < TT; t0 += 64) {
        __syncthreads();
        // stage K (transposed) and V (natural)
        #pragma unroll
        for (int i = 0; i < 16; i++) {
            const int e = tid + i * 256;
            const int t = e >> 6, d = e & 63;
            k_s[d * SM_STRIDE + t] = Kp[(size_t)(t0 + t) * DH + d];
            v_s[t * SM_STRIDE + d] = Vp[(size_t)(t0 + t) * DH + d];
        }
        __syncthreads();

        // S = lq @ K^T  (64l x 64t)
        {
            float acc[4][4] = {};
            #pragma unroll
            for (int d = 0; d < 64; d++) {
                float a[4], bq[4];
                #pragma unroll
                for (int i = 0; i < 4; i++) a[i]  = lq_s[d * SM_STRIDE + ty*4 + i];
                #pragma unroll
                for (int j = 0; j < 4; j++) bq[j] = k_s [d * SM_STRIDE + tx*4 + j];
                #pragma unroll
                for (int i = 0; i < 4; i++)
                    #pragma unroll
                    for (int j = 0; j < 4; j++) acc[i][j] += a[i] * bq[j];
            }
            #pragma unroll
            for (int i = 0; i < 4; i++)
                #pragma unroll
                for (int j = 0; j < 4; j++)
                    s_s[(ty*4 + i) * SM_STRIDE + tx*4 + j] = acc[i][j];
        }
        __syncthreads();

        // online masked softmax: 4 threads per row, 16 t-values each
        {
            const int* mrow = mk + (size_t)row * TT + t0 + sub * 16;
            int mb[16];
            #pragma unroll
            for (int q4 = 0; q4 < 4; q4++)
                *(int4*)&mb[q4 * 4] = *(const int4*)&mrow[q4 * 4];

            float sv[16];
            float tmax = -1e9f;
            #pragma unroll
            for (int q = 0; q < 16; q++) {
                float s = s_s[row * SM_STRIDE + sub * 16 + q];
                s = mb[q] ? s : -1e9f;
                sv[q] = s;
                tmax = fmaxf(tmax, s);
            }
            tmax = fmaxf(tmax, __shfl_xor_sync(0xffffffffu, tmax, 1));
            tmax = fmaxf(tmax, __shfl_xor_sync(0xffffffffu, tmax, 2));

            const float m_old = m_s[row];
            const float m_new = fmaxf(m_old, tmax);

            float psum = 0.f;
            #pragma unroll
            for (int q = 0; q < 16; q++) {
                const float p = mb[q] ? __expf(sv[q] - m_new) : 0.f;
                s_s[row * SM_STRIDE + sub * 16 + q] = p;
                psum += p;
            }
            psum += __shfl_xor_sync(0xffffffffu, psum, 1);
            psum += __shfl_xor_sync(0xffffffffu, psum, 2);

            if (sub == 0) {
                const float corr = __expf(m_old - m_new);
                c_s[row] = corr;
                m_s[row] = m_new;
                l_s[row] = l_s[row] * corr + psum;
            }
        }
        __syncthreads();

        // O = O*corr + P @ V
        {
            #pragma unroll
            for (int i = 0; i < 4; i++) {
                const float c = c_s[ty*4 + i];
                #pragma unroll
                for (int j = 0; j < 4; j++) O[i][j] *= c;
            }
            #pragma unroll
            for (int t = 0; t < 64; t++) {
                float p[4], vv[4];
                #pragma unroll
                for (int i = 0; i < 4; i++) p[i]  = s_s[(ty*4 + i) * SM_STRIDE + t];
                #pragma unroll
                for (int j = 0; j < 4; j++) vv[j] = v_s[t * SM_STRIDE + tx*4 + j];
                #pragma unroll
                for (int i = 0; i < 4; i++)
                    #pragma unroll
                    for (int j = 0; j < 4; j++) O[i][j] += p[i] * vv[j];
            }
        }
    }
    __syncthreads();

    // epilogue: out[b][lt*64+l][h*64+d] = O / l_sum  (0 if fully masked)
    #pragma unroll
    for (int i = 0; i < 4; i++) {
        const int l = ty*4 + i;
        const float denom = l_s[l];
        const float inv = denom > 0.f ? 1.f / denom : 0.f;
        float4 o4;
        o4.x = O[i][0] * inv; o4.y = O[i][1] * inv;
        o4.z = O[i][2] * inv; o4.w = O[i][3] * inv;
        const size_t oidx = (((size_t)b * LL + lt * 64 + l) * (size_t)DEMB) + h * 64 + tx * 4;
        *(float4*)&out[oidx] = o4;
    }
}

extern "C" void kernel_launch(void* const* d_in, const int* in_sizes, int n_in,
                              void* d_out, int out_size)
{
    const float* x    = (const float*)d_in[0];
    const int*   msk  = (const int*)d_in[1];
    const float* latq = (const float*)d_in[2];
    const float* wk   = (const float*)d_in[3];
    const float* bk   = (const float*)d_in[4];
    const float* wv   = (const float*)d_in[5];
    const float* bv   = (const float*)d_in[6];
    float*       out  = (float*)d_out;

    cudaFuncSetAttribute(attn_kernel, cudaFuncAttributeMaxDynamicSharedMemorySize,
                         (int)SMEM_ATTN);

    dim3 pgrid(DEMB / 64, (BB * TT) / 64, 2);
    proj_kernel<<<pgrid, 256>>>(x, wk, bk, wv, bv);

    dim3 agrid(LL / 64, NH, BB);
    attn_kernel<<<agrid, 256, SMEM_ATTN>>>(latq, msk, out);
}

// round 4
// speedup vs baseline: 4.3125x; 4.3125x over previous
#include <cuda_runtime.h>
#include <cstdint>

#define BB 4
#define TT 1024
#define DEMB 1024
#define NH 16
#define DH 64
#define LL 1344
#define BH 64          // BB*NH

#define BM 128
#define BN 64
#define BKF 32         // K floats per chunk
#define ASTR 36        // smem row stride (floats), conflict-free for frag loads

// Scratch (static __device__ globals; no runtime allocation).
__device__ float g_K [(size_t)BH * TT * DH];   // [b,h,t,d]
__device__ float g_Vt[(size_t)BH * DH * TT];   // [b,h,d,t]
__device__ float g_S [(size_t)BH * LL * TT];   // scores / weights

// dynamic smem layout in floats
#define A_OFF0 0
#define B_OFF0 (BM * ASTR)              // 4608
#define A_OFF1 (B_OFF0 + BN * ASTR)     // 6912
#define B_OFF1 (A_OFF1 + BM * ASTR)     // 11520
#define BIAS_OFF (B_OFF1 + BN * ASTR)   // 13824
#define SMEMF (BIAS_OFF + 64)
#define SMEMB (SMEMF * 4)

static __device__ __forceinline__ float f2tf(float f) {
    uint32_t r; asm("cvt.rna.tf32.f32 %0, %1;" : "=r"(r) : "f"(f));
    return __uint_as_float(r);
}

static __device__ __forceinline__ void mma8(float* c, const uint32_t* a, const uint32_t* b) {
    asm volatile("mma.sync.aligned.m16n8k8.row.col.f32.tf32.tf32.f32 "
                 "{%0,%1,%2,%3}, {%4,%5,%6,%7}, {%8,%9}, {%0,%1,%2,%3};"
                 : "+f"(c[0]), "+f"(c[1]), "+f"(c[2]), "+f"(c[3])
                 : "r"(a[0]), "r"(a[1]), "r"(a[2]), "r"(a[3]), "r"(b[0]), "r"(b[1]));
}

// One BK=32 chunk: 4 k-steps x (2 m-tiles x 4 n-tiles) mma
static __device__ __forceinline__ void compute_chunk(const float* __restrict__ As,
                                                     const float* __restrict__ Bs,
                                                     float c[2][4][4],
                                                     int wm, int wn, int g, int tig)
{
    #pragma unroll
    for (int ks = 0; ks < 4; ks++) {
        const int kb = ks * 8;
        uint32_t a[2][4], b[4][2];
        #pragma unroll
        for (int i = 0; i < 2; i++) {
            const float* p = As + (wm * 32 + i * 16 + g) * ASTR + kb + tig;
            a[i][0] = __float_as_uint(p[0]);
            a[i][1] = __float_as_uint(p[8 * ASTR]);
            a[i][2] = __float_as_uint(p[4]);
            a[i][3] = __float_as_uint(p[8 * ASTR + 4]);
        }
        #pragma unroll
        for (int j = 0; j < 4; j++) {
            const float* p = Bs + (wn * 32 + j * 8 + g) * ASTR + kb + tig;
            b[j][0] = __float_as_uint(p[0]);
            b[j][1] = __float_as_uint(p[4]);
        }
        #pragma unroll
        for (int i = 0; i < 2; i++)
            #pragma unroll
            for (int j = 0; j < 4; j++)
                mma8(c[i][j], a[i], b[j]);
    }
}

static __device__ __forceinline__ void sts_chunk(float* __restrict__ sm, int aoff, int boff,
                                                 const float4* pa, const float4* pb, int tid)
{
    #pragma unroll
    for (int jj = 0; jj < 4; jj++) {
        const int idx = tid + jj * 256;
        const int row = idx >> 3, f4 = idx & 7;
        float* d = sm + aoff + row * ASTR + f4 * 4;
        d[0] = f2tf(pa[jj].x); d[1] = f2tf(pa[jj].y);
        d[2] = f2tf(pa[jj].z); d[3] = f2tf(pa[jj].w);
    }
    #pragma unroll
    for (int jj = 0; jj < 2; jj++) {
        const int idx = tid + jj * 256;
        const int row = idx >> 3, f4 = idx & 7;
        float* d = sm + boff + row * ASTR + f4 * 4;
        d[0] = f2tf(pb[jj].x); d[1] = f2tf(pb[jj].y);
        d[2] = f2tf(pb[jj].z); d[3] = f2tf(pb[jj].w);
    }
}

// ---------------------------------------------------------------------------
// GEMM 1: projections. C[4096 x 1024] = X @ W^T (+bias). z=0 -> K, z=1 -> V^T.
// ---------------------------------------------------------------------------
__global__ __launch_bounds__(256)
void proj_kernel(const float* __restrict__ x,
                 const float* __restrict__ wk, const float* __restrict__ bk,
                 const float* __restrict__ wv, const float* __restrict__ bv)
{
    extern __shared__ float sm[];
    const int which = blockIdx.z;
    const float* __restrict__ w    = which ? wv : wk;
    const float* __restrict__ bias = which ? bv : bk;

    const int m0 = blockIdx.x * BM;
    const int n0 = blockIdx.y * BN;
    const int tid = threadIdx.x;
    const int warp = tid >> 5, lane = tid & 31;
    const int wm = warp >> 1, wn = warp & 1;
    const int g = lane >> 2, tig = lane & 3;

    if (tid < 64) sm[BIAS_OFF + tid] = bias[n0 + tid];

    float c[2][4][4] = {};
    float4 pa[4], pb[2];

    const int NC = DEMB / BKF;  // 32

    // prime chunk 0
    #pragma unroll
    for (int jj = 0; jj < 4; jj++) {
        const int idx = tid + jj * 256, row = idx >> 3, f4 = idx & 7;
        pa[jj] = *(const float4*)&x[(size_t)(m0 + row) * DEMB + f4 * 4];
    }
    #pragma unroll
    for (int jj = 0; jj < 2; jj++) {
        const int idx = tid + jj * 256, row = idx >> 3, f4 = idx & 7;
        pb[jj] = *(const float4*)&w[(size_t)(n0 + row) * DEMB + f4 * 4];
    }
    sts_chunk(sm, A_OFF0, B_OFF0, pa, pb, tid);
    __syncthreads();

    for (int cc = 0; cc < NC; cc++) {
        const int cur = cc & 1;
        if (cc + 1 < NC) {
            const int kofs = (cc + 1) * BKF;
            #pragma unroll
            for (int jj = 0; jj < 4; jj++) {
                const int idx = tid + jj * 256, row = idx >> 3, f4 = idx & 7;
                pa[jj] = *(const float4*)&x[(size_t)(m0 + row) * DEMB + kofs + f4 * 4];
            }
            #pragma unroll
            for (int jj = 0; jj < 2; jj++) {
                const int idx = tid + jj * 256, row = idx >> 3, f4 = idx & 7;
                pb[jj] = *(const float4*)&w[(size_t)(n0 + row) * DEMB + kofs + f4 * 4];
            }
        }
        compute_chunk(sm + (cur ? A_OFF1 : A_OFF0), sm + (cur ? B_OFF1 : B_OFF0), c, wm, wn, g, tig);
        if (cc + 1 < NC)
            sts_chunk(sm, cur ? A_OFF0 : A_OFF1, cur ? B_OFF0 : B_OFF1, pa, pb, tid);
        __syncthreads();
    }

    // epilogue
    const int b_ = m0 >> 10;
    const int h  = blockIdx.y;
    #pragma unroll
    for (int i = 0; i < 2; i++) {
        const int m1 = m0 + wm * 32 + i * 16 + g;
        const int t1 = m1 & 1023, t2 = (m1 + 8) & 1023;
        #pragma unroll
        for (int j = 0; j < 4; j++) {
            const int nl = wn * 32 + j * 8 + tig * 2;
            const float bz0 = sm[BIAS_OFF + nl], bz1 = sm[BIAS_OFF + nl + 1];
            if (which == 0) {
                float* d0 = g_K + (((size_t)(b_ * NH + h) * TT + t1) * DH) + nl;
                float* d1 = g_K + (((size_t)(b_ * NH + h) * TT + t2) * DH) + nl;
                float2 v0 = { c[i][j][0] + bz0, c[i][j][1] + bz1 };
                float2 v1 = { c[i][j][2] + bz0, c[i][j][3] + bz1 };
                *(float2*)d0 = v0;
                *(float2*)d1 = v1;
            } else {
                float* base = g_Vt + ((size_t)(b_ * NH + h) * DH) * TT;
                base[(size_t)nl * TT + t1]       = c[i][j][0] + bz0;
                base[(size_t)(nl + 1) * TT + t1] = c[i][j][1] + bz1;
                base[(size_t)nl * TT + t2]       = c[i][j][2] + bz0;
                base[(size_t)(nl + 1) * TT + t2] = c[i][j][3] + bz1;
            }
        }
    }
}

// ---------------------------------------------------------------------------
// GEMM 2: scores. per (b,h): S[l,t] = 0.25 * lq[l,:] . K[t,:]   (K-dim = 64)
// grid (11, 16, 64): x = l-tile (guarded at 1344), y = t-tile, z = b*16+h
// ---------------------------------------------------------------------------
__global__ __launch_bounds__(256)
void scores_kernel(const float* __restrict__ latq)
{
    extern __shared__ float sm[];
    const int m0 = blockIdx.x * BM;
    const int n0 = blockIdx.y * BN;
    const int bz = blockIdx.z;
    const int h  = bz & 15;
    const int tid = threadIdx.x;
    const int warp = tid >> 5, lane = tid & 31;
    const int wm = warp >> 1, wn = warp & 1;
    const int g = lane >> 2, tig = lane & 3;

    const float* __restrict__ A = latq + (size_t)h * (LL * DH);
    const float* __restrict__ B = g_K + (size_t)bz * TT * DH;

    float c[2][4][4] = {};
    float4 pa[4], pb[2];
    const int NC = DH / BKF;  // 2

    #pragma unroll
    for (int jj = 0; jj < 4; jj++) {
        const int idx = tid + jj * 256, row = idx >> 3, f4 = idx & 7;
        float4 v = {0.f, 0.f, 0.f, 0.f};
        if (m0 + row < LL) {
            v = *(const float4*)&A[(size_t)(m0 + row) * DH + f4 * 4];
            v.x *= 0.25f; v.y *= 0.25f; v.z *= 0.25f; v.w *= 0.25f;
        }
        pa[jj] = v;
    }
    #pragma unroll
    for (int jj = 0; jj < 2; jj++) {
        const int idx = tid + jj * 256, row = idx >> 3, f4 = idx & 7;
        pb[jj] = *(const float4*)&B[(size_t)(n0 + row) * DH + f4 * 4];
    }
    sts_chunk(sm, A_OFF0, B_OFF0, pa, pb, tid);
    __syncthreads();

    for (int cc = 0; cc < NC; cc++) {
        const int cur = cc & 1;
        if (cc + 1 < NC) {
            const int kofs = (cc + 1) * BKF;
            #pragma unroll
            for (int jj = 0; jj < 4; jj++) {
                const int idx = tid + jj * 256, row = idx >> 3, f4 = idx & 7;
                float4 v = {0.f, 0.f, 0.f, 0.f};
                if (m0 + row < LL) {
                    v = *(const float4*)&A[(size_t)(m0 + row) * DH + kofs + f4 * 4];
                    v.x *= 0.25f; v.y *= 0.25f; v.z *= 0.25f; v.w *= 0.25f;
                }
                pa[jj] = v;
            }
            #pragma unroll
            for (int jj = 0; jj < 2; jj++) {
                const int idx = tid + jj * 256, row = idx >> 3, f4 = idx & 7;
                pb[jj] = *(const float4*)&B[(size_t)(n0 + row) * DH + kofs + f4 * 4];
            }
        }
        compute_chunk(sm + (cur ? A_OFF1 : A_OFF0), sm + (cur ? B_OFF1 : B_OFF0), c, wm, wn, g, tig);
        if (cc + 1 < NC)
            sts_chunk(sm, cur ? A_OFF0 : A_OFF1, cur ? B_OFF0 : B_OFF1, pa, pb, tid);
        __syncthreads();
    }

    #pragma unroll
    for (int i = 0; i < 2; i++) {
        const int l1 = m0 + wm * 32 + i * 16 + g;
        #pragma unroll
        for (int j = 0; j < 4; j++) {
            const int nl = wn * 32 + j * 8 + tig * 2;
            if (l1 < LL) {
                float2 v0 = { c[i][j][0], c[i][j][1] };
                *(float2*)(g_S + ((size_t)bz * LL + l1) * TT + n0 + nl) = v0;
            }
            if (l1 + 8 < LL) {
                float2 v1 = { c[i][j][2], c[i][j][3] };
                *(float2*)(g_S + ((size_t)bz * LL + l1 + 8) * TT + n0 + nl) = v1;
            }
        }
    }
}

// ---------------------------------------------------------------------------
// Masked softmax over t, in place on g_S. One (b,l) per block; 8 warps x 2 heads.
// ---------------------------------------------------------------------------
__global__ __launch_bounds__(256)
void softmax_kernel(const int* __restrict__ mask)
{
    const int bl = blockIdx.x;
    const int b = bl / LL, l = bl - b * LL;
    const int warp = threadIdx.x >> 5, lane = threadIdx.x & 31;

    const int* __restrict__ M = mask + ((size_t)b * LL + l) * TT;
    int4 mv[8];
    #pragma unroll
    for (int j = 0; j < 8; j++)
        mv[j] = *(const int4*)(M + j * 128 + lane * 4);

    #pragma unroll
    for (int hh = 0; hh < 2; hh++) {
        const int h = warp * 2 + hh;
        float* S = g_S + ((size_t)(b * NH + h) * LL + l) * TT;
        float4 sv[8];
        #pragma unroll
        for (int j = 0; j < 8; j++)
            sv[j] = *(const float4*)(S + j * 128 + lane * 4);

        float mx = -3.0e38f;
        #pragma unroll
        for (int j = 0; j < 8; j++) {
            if (mv[j].x) mx = fmaxf(mx, sv[j].x);
            if (mv[j].y) mx = fmaxf(mx, sv[j].y);
            if (mv[j].z) mx = fmaxf(mx, sv[j].z);
            if (mv[j].w) mx = fmaxf(mx, sv[j].w);
        }
        #pragma unroll
        for (int o = 16; o; o >>= 1) mx = fmaxf(mx, __shfl_xor_sync(0xffffffffu, mx, o));

        float sum = 0.f;
        #pragma unroll
        for (int j = 0; j < 8; j++) {
            sv[j].x = mv[j].x ? __expf(sv[j].x - mx) : 0.f; sum += sv[j].x;
            sv[j].y = mv[j].y ? __expf(sv[j].y - mx) : 0.f; sum += sv[j].y;
            sv[j].z = mv[j].z ? __expf(sv[j].z - mx) : 0.f; sum += sv[j].z;
            sv[j].w = mv[j].w ? __expf(sv[j].w - mx) : 0.f; sum += sv[j].w;
        }
        #pragma unroll
        for (int o = 16; o; o >>= 1) sum += __shfl_xor_sync(0xffffffffu, sum, o);
        const float inv = sum > 0.f ? __frcp_rn(sum) : 0.f;

        #pragma unroll
        for (int j = 0; j < 8; j++) {
            float4 o4 = { sv[j].x * inv, sv[j].y * inv, sv[j].z * inv, sv[j].w * inv };
            *(float4*)(S + j * 128 + lane * 4) = o4;
        }
    }
}

// ---------------------------------------------------------------------------
// GEMM 3: out. per (b,h): O[l,d] = W[l,:] . Vt[d,:]   (K-dim = T = 1024)
// grid (11, 64): x = l-tile (guarded), y = b*16+h
// ---------------------------------------------------------------------------
__global__ __launch_bounds__(256)
void out_kernel(float* __restrict__ out)
{
    extern __shared__ float sm[];
    const int m0 = blockIdx.x * BM;
    const int bz = blockIdx.y;
    const int b  = bz >> 4, h = bz & 15;
    const int tid = threadIdx.x;
    const int warp = tid >> 5, lane = tid & 31;
    const int wm = warp >> 1, wn = warp & 1;
    const int g = lane >> 2, tig = lane & 3;

    const float* __restrict__ A = g_S + (size_t)bz * LL * TT;
    const float* __restrict__ B = g_Vt + (size_t)bz * DH * TT;

    float c[2][4][4] = {};
    float4 pa[4], pb[2];
    const int NC = TT / BKF;  // 32

    #pragma unroll
    for (int jj = 0; jj < 4; jj++) {
        const int idx = tid + jj * 256, row = idx >> 3, f4 = idx & 7;
        float4 v = {0.f, 0.f, 0.f, 0.f};
        if (m0 + row < LL) v = *(const float4*)&A[(size_t)(m0 + row) * TT + f4 * 4];
        pa[jj] = v;
    }
    #pragma unroll
    for (int jj = 0; jj < 2; jj++) {
        const int idx = tid + jj * 256, row = idx >> 3, f4 = idx & 7;
        pb[jj] = *(const float4*)&B[(size_t)row * TT + f4 * 4];
    }
    sts_chunk(sm, A_OFF0, B_OFF0, pa, pb, tid);
    __syncthreads();

    for (int cc = 0; cc < NC; cc++) {
        const int cur = cc & 1;
        if (cc + 1 < NC) {
            const int kofs = (cc + 1) * BKF;
            #pragma unroll
            for (int jj = 0; jj < 4; jj++) {
                const int idx = tid + jj * 256, row = idx >> 3, f4 = idx & 7;
                float4 v = {0.f, 0.f, 0.f, 0.f};
                if (m0 + row < LL) v = *(const float4*)&A[(size_t)(m0 + row) * TT + kofs + f4 * 4];
                pa[jj] = v;
            }
            #pragma unroll
            for (int jj = 0; jj < 2; jj++) {
                const int idx = tid + jj * 256, row = idx >> 3, f4 = idx & 7;
                pb[jj] = *(const float4*)&B[(size_t)row * TT + kofs + f4 * 4];
            }
        }
        compute_chunk(sm + (cur ? A_OFF1 : A_OFF0), sm + (cur ? B_OFF1 : B_OFF0), c, wm, wn, g, tig);
        if (cc + 1 < NC)
            sts_chunk(sm, cur ? A_OFF0 : A_OFF1, cur ? B_OFF0 : B_OFF1, pa, pb, tid);
        __syncthreads();
    }

    #pragma unroll
    for (int i = 0; i < 2; i++) {
        const int l1 = m0 + wm * 32 + i * 16 + g;
        #pragma unroll
        for (int j = 0; j < 4; j++) {
            const int nl = wn * 32 + j * 8 + tig * 2;
            if (l1 < LL) {
                float2 v0 = { c[i][j][0], c[i][j][1] };
                *(float2*)(out + ((size_t)b * LL + l1) * DEMB + h * DH + nl) = v0;
            }
            if (l1 + 8 < LL) {
                float2 v1 = { c[i][j][2], c[i][j][3] };
                *(float2*)(out + ((size_t)b * LL + l1 + 8) * DEMB + h * DH + nl) = v1;
            }
        }
    }
}

// ---------------------------------------------------------------------------
extern "C" void kernel_launch(void* const* d_in, const int* in_sizes, int n_in,
                              void* d_out, int out_size)
{
    const float* x    = (const float*)d_in[0];
    const int*   msk  = (const int*)d_in[1];
    const float* latq = (const float*)d_in[2];
    const float* wk   = (const float*)d_in[3];
    const float* bk   = (const float*)d_in[4];
    const float* wv   = (const float*)d_in[5];
    const float* bv   = (const float*)d_in[6];
    float*       out  = (float*)d_out;

    cudaFuncSetAttribute(proj_kernel,   cudaFuncAttributeMaxDynamicSharedMemorySize, SMEMB);
    cudaFuncSetAttribute(scores_kernel, cudaFuncAttributeMaxDynamicSharedMemorySize, SMEMB);
    cudaFuncSetAttribute(out_kernel,    cudaFuncAttributeMaxDynamicSharedMemorySize, SMEMB);

    proj_kernel  <<<dim3(32, 16, 2),  256, SMEMB>>>(x, wk, bk, wv, bv);
    scores_kernel<<<dim3(11, 16, 64), 256, SMEMB>>>(latq);
    softmax_kernel<<<BB * LL, 256>>>(msk);
    out_kernel   <<<dim3(11, 64),     256, SMEMB>>>(out);
}

// round 5
// speedup vs baseline: 5.6421x; 1.3083x over previous
#include <cuda_runtime.h>
#include <cstdint>

#define BB 4
#define TT 1024
#define DEMB 1024
#define NH 16
#define DH 64
#define LL 1344
#define BH 64          // BB*NH

#define BM 128
#define BN 64
#define BKF 32         // proj K floats per chunk
#define ASTR 36        // proj smem stride
#define FSTR 68        // fused kernel smem stride (64 + 4)

// Scratch (static __device__ globals; no runtime allocation).
__device__ float    g_K [(size_t)BH * TT * DH];   // [b,h,t,d]
__device__ float    g_Vt[(size_t)BH * DH * TT];   // [b,h,d,t]
__device__ uint32_t g_Mp[(size_t)BB * LL * (TT / 32)];  // packed mask bits

// proj smem layout (floats)
#define A_OFF0 0
#define B_OFF0 (BM * ASTR)
#define A_OFF1 (B_OFF0 + BN * ASTR)
#define B_OFF1 (A_OFF1 + BM * ASTR)
#define BIAS_OFF (B_OFF1 + BN * ASTR)
#define SMEMF (BIAS_OFF + 64)
#define SMEMB (SMEMF * 4)

// fused smem layout (floats)
#define LQ_OFF  0
#define KS_OFF  (BM * FSTR)                 // 8704
#define VS_OFF  (KS_OFF + 64 * FSTR)        // 13056
#define PS_OFF  (VS_OFF + 64 * FSTR)        // 17408
#define MS_OFF  (PS_OFF + BM * FSTR)        // 26112
#define LS_OFF  (MS_OFF + 128)
#define RMAX_OFF (LS_OFF + 128)
#define RSUM_OFF (RMAX_OFF + 256)
#define SMEM_ATT_B ((RSUM_OFF + 256) * 4)   // 107520 bytes

static __device__ __forceinline__ float f2tf(float f) {
    uint32_t r; asm("cvt.rna.tf32.f32 %0, %1;" : "=r"(r) : "f"(f));
    return __uint_as_float(r);
}

static __device__ __forceinline__ void mma8(float* c, const uint32_t* a, const uint32_t* b) {
    asm volatile("mma.sync.aligned.m16n8k8.row.col.f32.tf32.tf32.f32 "
                 "{%0,%1,%2,%3}, {%4,%5,%6,%7}, {%8,%9}, {%0,%1,%2,%3};"
                 : "+f"(c[0]), "+f"(c[1]), "+f"(c[2]), "+f"(c[3])
                 : "r"(a[0]), "r"(a[1]), "r"(a[2]), "r"(a[3]), "r"(b[0]), "r"(b[1]));
}

// Generic: KSTEPS k-steps of 8, A/B smem with stride STR.
template<int STR, int KSTEPS>
static __device__ __forceinline__ void compute_mma(const float* __restrict__ As,
                                                   const float* __restrict__ Bs,
                                                   float c[2][4][4],
                                                   int wm, int wn, int g, int tig)
{
    #pragma unroll
    for (int ks = 0; ks < KSTEPS; ks++) {
        const int kb = ks * 8;
        uint32_t a[2][4], b[4][2];
        #pragma unroll
        for (int i = 0; i < 2; i++) {
            const float* p = As + (wm * 32 + i * 16 + g) * STR + kb + tig;
            a[i][0] = __float_as_uint(p[0]);
            a[i][1] = __float_as_uint(p[8 * STR]);
            a[i][2] = __float_as_uint(p[4]);
            a[i][3] = __float_as_uint(p[8 * STR + 4]);
        }
        #pragma unroll
        for (int j = 0; j < 4; j++) {
            const float* p = Bs + (wn * 32 + j * 8 + g) * STR + kb + tig;
            b[j][0] = __float_as_uint(p[0]);
            b[j][1] = __float_as_uint(p[4]);
        }
        #pragma unroll
        for (int i = 0; i < 2; i++)
            #pragma unroll
            for (int j = 0; j < 4; j++)
                mma8(c[i][j], a[i], b[j]);
    }
}

static __device__ __forceinline__ void sts_chunk(float* __restrict__ sm, int aoff, int boff,
                                                 const float4* pa, const float4* pb, int tid)
{
    #pragma unroll
    for (int jj = 0; jj < 4; jj++) {
        const int idx = tid + jj * 256;
        const int row = idx >> 3, f4 = idx & 7;
        float* d = sm + aoff + row * ASTR + f4 * 4;
        d[0] = f2tf(pa[jj].x); d[1] = f2tf(pa[jj].y);
        d[2] = f2tf(pa[jj].z); d[3] = f2tf(pa[jj].w);
    }
    #pragma unroll
    for (int jj = 0; jj < 2; jj++) {
        const int idx = tid + jj * 256;
        const int row = idx >> 3, f4 = idx & 7;
        float* d = sm + boff + row * ASTR + f4 * 4;
        d[0] = f2tf(pb[jj].x); d[1] = f2tf(pb[jj].y);
        d[2] = f2tf(pb[jj].z); d[3] = f2tf(pb[jj].w);
    }
}

// ---------------------------------------------------------------------------
// Mask pack: int32 [b,l,t] -> bit per t.  One warp per (b,l) row.
// ---------------------------------------------------------------------------
__global__ __launch_bounds__(256)
void pack_mask(const int* __restrict__ mask)
{
    const int row = blockIdx.x * 8 + (threadIdx.x >> 5);
    const int lane = threadIdx.x & 31;
    const int* __restrict__ M = mask + (size_t)row * TT;
    uint32_t myword = 0;
    #pragma unroll
    for (int w = 0; w < 32; w++) {
        uint32_t bal = __ballot_sync(0xffffffffu, M[w * 32 + lane] != 0);
        if (lane == w) myword = bal;
    }
    g_Mp[(size_t)row * 32 + lane] = myword;
}

// ---------------------------------------------------------------------------
// GEMM 1: projections. C[4096 x 1024] = X @ W^T (+bias). z=0 -> K, z=1 -> V^T.
// ---------------------------------------------------------------------------
__global__ __launch_bounds__(256)
void proj_kernel(const float* __restrict__ x,
                 const float* __restrict__ wk, const float* __restrict__ bk,
                 const float* __restrict__ wv, const float* __restrict__ bv)
{
    extern __shared__ float sm[];
    const int which = blockIdx.z;
    const float* __restrict__ w    = which ? wv : wk;
    const float* __restrict__ bias = which ? bv : bk;

    const int m0 = blockIdx.x * BM;
    const int n0 = blockIdx.y * BN;
    const int tid = threadIdx.x;
    const int warp = tid >> 5, lane = tid & 31;
    const int wm = warp >> 1, wn = warp & 1;
    const int g = lane >> 2, tig = lane & 3;

    if (tid < 64) sm[BIAS_OFF + tid] = bias[n0 + tid];

    float c[2][4][4] = {};
    float4 pa[4], pb[2];
    const int NC = DEMB / BKF;  // 32

    #pragma unroll
    for (int jj = 0; jj < 4; jj++) {
        const int idx = tid + jj * 256, row = idx >> 3, f4 = idx & 7;
        pa[jj] = *(const float4*)&x[(size_t)(m0 + row) * DEMB + f4 * 4];
    }
    #pragma unroll
    for (int jj = 0; jj < 2; jj++) {
        const int idx = tid + jj * 256, row = idx >> 3, f4 = idx & 7;
        pb[jj] = *(const float4*)&w[(size_t)(n0 + row) * DEMB + f4 * 4];
    }
    sts_chunk(sm, A_OFF0, B_OFF0, pa, pb, tid);
    __syncthreads();

    for (int cc = 0; cc < NC; cc++) {
        const int cur = cc & 1;
        if (cc + 1 < NC) {
            const int kofs = (cc + 1) * BKF;
            #pragma unroll
            for (int jj = 0; jj < 4; jj++) {
                const int idx = tid + jj * 256, row = idx >> 3, f4 = idx & 7;
                pa[jj] = *(const float4*)&x[(size_t)(m0 + row) * DEMB + kofs + f4 * 4];
            }
            #pragma unroll
            for (int jj = 0; jj < 2; jj++) {
                const int idx = tid + jj * 256, row = idx >> 3, f4 = idx & 7;
                pb[jj] = *(const float4*)&w[(size_t)(n0 + row) * DEMB + kofs + f4 * 4];
            }
        }
        compute_mma<ASTR, 4>(sm + (cur ? A_OFF1 : A_OFF0), sm + (cur ? B_OFF1 : B_OFF0),
                             c, wm, wn, g, tig);
        if (cc + 1 < NC)
            sts_chunk(sm, cur ? A_OFF0 : A_OFF1, cur ? B_OFF0 : B_OFF1, pa, pb, tid);
        __syncthreads();
    }

    const int b_ = m0 >> 10;
    const int h  = blockIdx.y;
    #pragma unroll
    for (int i = 0; i < 2; i++) {
        const int m1 = m0 + wm * 32 + i * 16 + g;
        const int t1 = m1 & 1023, t2 = (m1 + 8) & 1023;
        #pragma unroll
        for (int j = 0; j < 4; j++) {
            const int nl = wn * 32 + j * 8 + tig * 2;
            const float bz0 = sm[BIAS_OFF + nl], bz1 = sm[BIAS_OFF + nl + 1];
            if (which == 0) {
                float* d0 = g_K + (((size_t)(b_ * NH + h) * TT + t1) * DH) + nl;
                float* d1 = g_K + (((size_t)(b_ * NH + h) * TT + t2) * DH) + nl;
                float2 v0 = { c[i][j][0] + bz0, c[i][j][1] + bz1 };
                float2 v1 = { c[i][j][2] + bz0, c[i][j][3] + bz1 };
                *(float2*)d0 = v0;
                *(float2*)d1 = v1;
            } else {
                float* base = g_Vt + ((size_t)(b_ * NH + h) * DH) * TT;
                base[(size_t)nl * TT + t1]       = c[i][j][0] + bz0;
                base[(size_t)(nl + 1) * TT + t1] = c[i][j][1] + bz1;
                base[(size_t)nl * TT + t2]       = c[i][j][2] + bz0;
                base[(size_t)(nl + 1) * TT + t2] = c[i][j][3] + bz1;
            }
        }
    }
}

// ---------------------------------------------------------------------------
// Fused flash attention: scores + masked softmax + P@V.
// grid (11, 64): x = l-tile (128, guarded at 1344), y = b*16+h.
// ---------------------------------------------------------------------------
__global__ __launch_bounds__(256)
void attn_fused(const float* __restrict__ latq, float* __restrict__ out)
{
    extern __shared__ float sm[];
    float* lq_s = sm + LQ_OFF;
    float* Ks   = sm + KS_OFF;
    float* Vs   = sm + VS_OFF;
    float* Ps   = sm + PS_OFF;
    float* m_s  = sm + MS_OFF;
    float* l_s  = sm + LS_OFF;
    float* rmax = sm + RMAX_OFF;
    float* rsum = sm + RSUM_OFF;

    const int m0 = blockIdx.x * BM;
    const int bz = blockIdx.y;
    const int b  = bz >> 4, h = bz & 15;
    const int tid = threadIdx.x;
    const int warp = tid >> 5, lane = tid & 31;
    const int wm = warp >> 1, wn = warp & 1;
    const int g = lane >> 2, tig = lane & 3;

    const float* __restrict__ A  = latq + (size_t)h * (LL * DH);
    const float* __restrict__ Kg = g_K  + (size_t)bz * TT * DH;
    const float* __restrict__ Vg = g_Vt + (size_t)bz * DH * TT;
    const uint32_t* __restrict__ Mp = g_Mp + (size_t)b * LL * 32;

    // stage lq (x0.25, tf32)
    #pragma unroll
    for (int jj = 0; jj < 8; jj++) {
        const int idx = tid + jj * 256;
        const int row = idx >> 4, f4 = idx & 15;
        float4 v = {0.f, 0.f, 0.f, 0.f};
        if (m0 + row < LL) {
            v = *(const float4*)&A[(size_t)(m0 + row) * DH + f4 * 4];
            v.x *= 0.25f; v.y *= 0.25f; v.z *= 0.25f; v.w *= 0.25f;
        }
        float* d = lq_s + row * FSTR + f4 * 4;
        d[0] = f2tf(v.x); d[1] = f2tf(v.y); d[2] = f2tf(v.z); d[3] = f2tf(v.w);
    }
    if (tid < 128) { m_s[tid] = -1e30f; l_s[tid] = 0.f; }

    float co[2][4][4] = {};
    __syncthreads();

    for (int tile = 0; tile < TT / 64; tile++) {
        const int t0 = tile * 64;
        // stage K tile [t][d] and V tile [d][t]
        #pragma unroll
        for (int jj = 0; jj < 4; jj++) {
            const int idx = tid + jj * 256;
            const int row = idx >> 4, f4 = idx & 15;
            float4 kv = *(const float4*)&Kg[(size_t)(t0 + row) * DH + f4 * 4];
            float* dk = Ks + row * FSTR + f4 * 4;
            dk[0] = f2tf(kv.x); dk[1] = f2tf(kv.y); dk[2] = f2tf(kv.z); dk[3] = f2tf(kv.w);
            float4 vv = *(const float4*)&Vg[(size_t)row * TT + t0 + f4 * 4];
            float* dv = Vs + row * FSTR + f4 * 4;
            dv[0] = f2tf(vv.x); dv[1] = f2tf(vv.y); dv[2] = f2tf(vv.z); dv[3] = f2tf(vv.w);
        }
        __syncthreads();

        // S = lq @ K^T
        float cs[2][4][4] = {};
        compute_mma<FSTR, 8>(lq_s, Ks, cs, wm, wn, g, tig);

        // mask words
        uint32_t mw[2][2];
        #pragma unroll
        for (int i = 0; i < 2; i++) {
            const int lA = m0 + wm * 32 + i * 16 + g;
            const int lB = lA + 8;
            mw[i][0] = (lA < LL) ? Mp[(size_t)lA * 32 + tile * 2 + wn] : 0u;
            mw[i][1] = (lB < LL) ? Mp[(size_t)lB * 32 + tile * 2 + wn] : 0u;
        }

        // local masked max + tig-shfl reduce, write rmax
        #pragma unroll
        for (int i = 0; i < 2; i++) {
            const int rA = wm * 32 + i * 16 + g, rB = rA + 8;
            float mxA = -1e30f, mxB = -1e30f;
            #pragma unroll
            for (int j = 0; j < 4; j++) {
                const int b0 = j * 8 + tig * 2;
                if ((mw[i][0] >> b0) & 1)       mxA = fmaxf(mxA, cs[i][j][0]);
                if ((mw[i][0] >> (b0 + 1)) & 1) mxA = fmaxf(mxA, cs[i][j][1]);
                if ((mw[i][1] >> b0) & 1)       mxB = fmaxf(mxB, cs[i][j][2]);
                if ((mw[i][1] >> (b0 + 1)) & 1) mxB = fmaxf(mxB, cs[i][j][3]);
            }
            mxA = fmaxf(mxA, __shfl_xor_sync(0xffffffffu, mxA, 1));
            mxA = fmaxf(mxA, __shfl_xor_sync(0xffffffffu, mxA, 2));
            mxB = fmaxf(mxB, __shfl_xor_sync(0xffffffffu, mxB, 1));
            mxB = fmaxf(mxB, __shfl_xor_sync(0xffffffffu, mxB, 2));
            if (tig == 0) { rmax[rA * 2 + wn] = mxA; rmax[rB * 2 + wn] = mxB; }
        }
        __syncthreads();

        // p = exp(s - m_new) (masked -> 0); write P to smem; scale O; row sums
        #pragma unroll
        for (int i = 0; i < 2; i++) {
            #pragma unroll
            for (int half = 0; half < 2; half++) {
                const int r = wm * 32 + i * 16 + g + half * 8;
                const uint32_t w32 = mw[i][half];
                const float mold = m_s[r];
                const float mnew = fmaxf(mold, fmaxf(rmax[r * 2], rmax[r * 2 + 1]));
                const float corr = __expf(mold - mnew);
                float srow = 0.f;
                #pragma unroll
                for (int j = 0; j < 4; j++) {
                    const int b0 = j * 8 + tig * 2;
                    const int k = half * 2;
                    const float p0 = ((w32 >> b0) & 1)       ? __expf(cs[i][j][k]     - mnew) : 0.f;
                    const float p1 = ((w32 >> (b0 + 1)) & 1) ? __expf(cs[i][j][k + 1] - mnew) : 0.f;
                    srow += p0 + p1;
                    float2 pv = { f2tf(p0), f2tf(p1) };
                    *(float2*)(Ps + r * FSTR + wn * 32 + b0) = pv;
                    co[i][j][k]     *= corr;
                    co[i][j][k + 1] *= corr;
                }
                srow += __shfl_xor_sync(0xffffffffu, srow, 1);
                srow += __shfl_xor_sync(0xffffffffu, srow, 2);
                if (tig == 0) rsum[r * 2 + wn] = srow;
            }
        }
        __syncthreads();

        // stats update (one thread per row)
        if (wn == 0 && tig == 0) {
            #pragma unroll
            for (int i = 0; i < 2; i++) {
                #pragma unroll
                for (int half = 0; half < 2; half++) {
                    const int r = wm * 32 + i * 16 + g + half * 8;
                    const float mold = m_s[r];
                    const float mnew = fmaxf(mold, fmaxf(rmax[r * 2], rmax[r * 2 + 1]));
                    m_s[r] = mnew;
                    l_s[r] = l_s[r] * __expf(mold - mnew) + rsum[r * 2] + rsum[r * 2 + 1];
                }
            }
        }

        // O += P @ V
        compute_mma<FSTR, 8>(Ps, Vs, co, wm, wn, g, tig);
        __syncthreads();
    }

    // epilogue: out[b, l, h*64 + d] = O / l_s  (0 if fully masked)
    #pragma unroll
    for (int i = 0; i < 2; i++) {
        const int rA = wm * 32 + i * 16 + g, rB = rA + 8;
        const int lA = m0 + rA, lB = m0 + rB;
        const float dA = l_s[rA], dB = l_s[rB];
        const float invA = dA > 0.f ? __frcp_rn(dA) : 0.f;
        const float invB = dB > 0.f ? __frcp_rn(dB) : 0.f;
        #pragma unroll
        for (int j = 0; j < 4; j++) {
            const int nl = wn * 32 + j * 8 + tig * 2;
            if (lA < LL) {
                float2 v0 = { co[i][j][0] * invA, co[i][j][1] * invA };
                *(float2*)(out + ((size_t)b * LL + lA) * DEMB + h * DH + nl) = v0;
            }
            if (lB < LL) {
                float2 v1 = { co[i][j][2] * invB, co[i][j][3] * invB };
                *(float2*)(out + ((size_t)b * LL + lB) * DEMB + h * DH + nl) = v1;
            }
        }
    }
}

// ---------------------------------------------------------------------------
extern "C" void kernel_launch(void* const* d_in, const int* in_sizes, int n_in,
                              void* d_out, int out_size)
{
    const float* x    = (const float*)d_in[0];
    const int*   msk  = (const int*)d_in[1];
    const float* latq = (const float*)d_in[2];
    const float* wk   = (const float*)d_in[3];
    const float* bk   = (const float*)d_in[4];
    const float* wv   = (const float*)d_in[5];
    const float* bv   = (const float*)d_in[6];
    float*       out  = (float*)d_out;

    cudaFuncSetAttribute(proj_kernel, cudaFuncAttributeMaxDynamicSharedMemorySize, SMEMB);
    cudaFuncSetAttribute(attn_fused,  cudaFuncAttributeMaxDynamicSharedMemorySize, SMEM_ATT_B);

    pack_mask<<<BB * LL / 8, 256>>>(msk);
    proj_kernel<<<dim3(32, 16, 2), 256, SMEMB>>>(x, wk, bk, wv, bv);
    attn_fused <<<dim3(11, 64),    256, SMEM_ATT_B>>>(latq, out);
}

// round 6
// speedup vs baseline: 6.3114x; 1.1186x over previous
#include <cuda_runtime.h>
#include <cstdint>

#define BB 4
#define TT 1024
#define DEMB 1024
#define NH 16
#define DH 64
#define LL 1344
#define BH 64          // BB*NH

#define BM 128
#define BN 64
#define BKF 32         // proj K floats per chunk
#define ASTR 36        // proj smem stride
#define FSTR 68        // fused kernel smem stride (64 + 4)

// Scratch (static __device__ globals; no runtime allocation).
__device__ float    g_K [(size_t)BH * TT * DH];   // [b,h,t,d]  (tf32-rounded)
__device__ float    g_Vt[(size_t)BH * DH * TT];   // [b,h,d,t]  (tf32-rounded)
__device__ uint32_t g_Mp[(size_t)BB * LL * (TT / 32)];  // packed mask bits

// proj smem layout (floats)
#define A_OFF0 0
#define B_OFF0 (BM * ASTR)
#define A_OFF1 (B_OFF0 + BN * ASTR)
#define B_OFF1 (A_OFF1 + BM * ASTR)
#define BIAS_OFF (B_OFF1 + BN * ASTR)
#define SMEMF (BIAS_OFF + 64)
#define SMEMB (SMEMF * 4)

// fused smem layout (floats)
#define LQ_OFF  0
#define KS_OFF  (BM * FSTR)                 // 8704
#define VS_OFF  (KS_OFF + 64 * FSTR)        // 13056
#define PS_OFF  (VS_OFF + 64 * FSTR)        // 17408
#define RSUM_OFF (PS_OFF + BM * FSTR)       // 26112
#define SMEM_ATT_B ((RSUM_OFF + 256) * 4)   // 105472 bytes

static __device__ __forceinline__ float f2tf(float f) {
    uint32_t r; asm("cvt.rna.tf32.f32 %0, %1;" : "=r"(r) : "f"(f));
    return __uint_as_float(r);
}

static __device__ __forceinline__ void mma8(float* c, const uint32_t* a, const uint32_t* b) {
    asm volatile("mma.sync.aligned.m16n8k8.row.col.f32.tf32.tf32.f32 "
                 "{%0,%1,%2,%3}, {%4,%5,%6,%7}, {%8,%9}, {%0,%1,%2,%3};"
                 : "+f"(c[0]), "+f"(c[1]), "+f"(c[2]), "+f"(c[3])
                 : "r"(a[0]), "r"(a[1]), "r"(a[2]), "r"(a[3]), "r"(b[0]), "r"(b[1]));
}

template<int STR, int KSTEPS>
static __device__ __forceinline__ void compute_mma(const float* __restrict__ As,
                                                   const float* __restrict__ Bs,
                                                   float c[2][4][4],
                                                   int wm, int wn, int g, int tig)
{
    #pragma unroll
    for (int ks = 0; ks < KSTEPS; ks++) {
        const int kb = ks * 8;
        uint32_t a[2][4], b[4][2];
        #pragma unroll
        for (int i = 0; i < 2; i++) {
            const float* p = As + (wm * 32 + i * 16 + g) * STR + kb + tig;
            a[i][0] = __float_as_uint(p[0]);
            a[i][1] = __float_as_uint(p[8 * STR]);
            a[i][2] = __float_as_uint(p[4]);
            a[i][3] = __float_as_uint(p[8 * STR + 4]);
        }
        #pragma unroll
        for (int j = 0; j < 4; j++) {
            const float* p = Bs + (wn * 32 + j * 8 + g) * STR + kb + tig;
            b[j][0] = __float_as_uint(p[0]);
            b[j][1] = __float_as_uint(p[4]);
        }
        #pragma unroll
        for (int i = 0; i < 2; i++)
            #pragma unroll
            for (int j = 0; j < 4; j++)
                mma8(c[i][j], a[i], b[j]);
    }
}

static __device__ __forceinline__ void sts_chunk(float* __restrict__ sm, int aoff, int boff,
                                                 const float4* pa, const float4* pb, int tid)
{
    #pragma unroll
    for (int jj = 0; jj < 4; jj++) {
        const int idx = tid + jj * 256;
        const int row = idx >> 3, f4 = idx & 7;
        float* d = sm + aoff + row * ASTR + f4 * 4;
        d[0] = f2tf(pa[jj].x); d[1] = f2tf(pa[jj].y);
        d[2] = f2tf(pa[jj].z); d[3] = f2tf(pa[jj].w);
    }
    #pragma unroll
    for (int jj = 0; jj < 2; jj++) {
        const int idx = tid + jj * 256;
        const int row = idx >> 3, f4 = idx & 7;
        float* d = sm + boff + row * ASTR + f4 * 4;
        d[0] = f2tf(pb[jj].x); d[1] = f2tf(pb[jj].y);
        d[2] = f2tf(pb[jj].z); d[3] = f2tf(pb[jj].w);
    }
}

// ---------------------------------------------------------------------------
// Mask pack: int32 [b,l,t] -> bit per t.  One warp per (b,l) row.
// ---------------------------------------------------------------------------
__global__ __launch_bounds__(256)
void pack_mask(const int* __restrict__ mask)
{
    const int row = blockIdx.x * 8 + (threadIdx.x >> 5);
    const int lane = threadIdx.x & 31;
    const int* __restrict__ M = mask + (size_t)row * TT;
    uint32_t myword = 0;
    #pragma unroll
    for (int w = 0; w < 32; w++) {
        uint32_t bal = __ballot_sync(0xffffffffu, M[w * 32 + lane] != 0);
        if (lane == w) myword = bal;
    }
    g_Mp[(size_t)row * 32 + lane] = myword;
}

// ---------------------------------------------------------------------------
// GEMM 1: projections. C[4096 x 1024] = X @ W^T (+bias). z=0 -> K, z=1 -> V^T.
// Results stored tf32-rounded (identical to what the attn mma would consume).
// ---------------------------------------------------------------------------
__global__ __launch_bounds__(256)
void proj_kernel(const float* __restrict__ x,
                 const float* __restrict__ wk, const float* __restrict__ bk,
                 const float* __restrict__ wv, const float* __restrict__ bv)
{
    extern __shared__ float sm[];
    const int which = blockIdx.z;
    const float* __restrict__ w    = which ? wv : wk;
    const float* __restrict__ bias = which ? bv : bk;

    const int m0 = blockIdx.x * BM;
    const int n0 = blockIdx.y * BN;
    const int tid = threadIdx.x;
    const int warp = tid >> 5, lane = tid & 31;
    const int wm = warp >> 1, wn = warp & 1;
    const int g = lane >> 2, tig = lane & 3;

    if (tid < 64) sm[BIAS_OFF + tid] = bias[n0 + tid];

    float c[2][4][4] = {};
    float4 pa[4], pb[2];
    const int NC = DEMB / BKF;  // 32

    #pragma unroll
    for (int jj = 0; jj < 4; jj++) {
        const int idx = tid + jj * 256, row = idx >> 3, f4 = idx & 7;
        pa[jj] = *(const float4*)&x[(size_t)(m0 + row) * DEMB + f4 * 4];
    }
    #pragma unroll
    for (int jj = 0; jj < 2; jj++) {
        const int idx = tid + jj * 256, row = idx >> 3, f4 = idx & 7;
        pb[jj] = *(const float4*)&w[(size_t)(n0 + row) * DEMB + f4 * 4];
    }
    sts_chunk(sm, A_OFF0, B_OFF0, pa, pb, tid);
    __syncthreads();

    for (int cc = 0; cc < NC; cc++) {
        const int cur = cc & 1;
        if (cc + 1 < NC) {
            const int kofs = (cc + 1) * BKF;
            #pragma unroll
            for (int jj = 0; jj < 4; jj++) {
                const int idx = tid + jj * 256, row = idx >> 3, f4 = idx & 7;
                pa[jj] = *(const float4*)&x[(size_t)(m0 + row) * DEMB + kofs + f4 * 4];
            }
            #pragma unroll
            for (int jj = 0; jj < 2; jj++) {
                const int idx = tid + jj * 256, row = idx >> 3, f4 = idx & 7;
                pb[jj] = *(const float4*)&w[(size_t)(n0 + row) * DEMB + kofs + f4 * 4];
            }
        }
        compute_mma<ASTR, 4>(sm + (cur ? A_OFF1 : A_OFF0), sm + (cur ? B_OFF1 : B_OFF0),
                             c, wm, wn, g, tig);
        if (cc + 1 < NC)
            sts_chunk(sm, cur ? A_OFF0 : A_OFF1, cur ? B_OFF0 : B_OFF1, pa, pb, tid);
        __syncthreads();
    }

    const int b_ = m0 >> 10;
    const int h  = blockIdx.y;
    #pragma unroll
    for (int i = 0; i < 2; i++) {
        const int m1 = m0 + wm * 32 + i * 16 + g;
        const int t1 = m1 & 1023, t2 = (m1 + 8) & 1023;
        #pragma unroll
        for (int j = 0; j < 4; j++) {
            const int nl = wn * 32 + j * 8 + tig * 2;
            const float bz0 = sm[BIAS_OFF + nl], bz1 = sm[BIAS_OFF + nl + 1];
            if (which == 0) {
                float* d0 = g_K + (((size_t)(b_ * NH + h) * TT + t1) * DH) + nl;
                float* d1 = g_K + (((size_t)(b_ * NH + h) * TT + t2) * DH) + nl;
                float2 v0 = { f2tf(c[i][j][0] + bz0), f2tf(c[i][j][1] + bz1) };
                float2 v1 = { f2tf(c[i][j][2] + bz0), f2tf(c[i][j][3] + bz1) };
                *(float2*)d0 = v0;
                *(float2*)d1 = v1;
            } else {
                float* base = g_Vt + ((size_t)(b_ * NH + h) * DH) * TT;
                base[(size_t)nl * TT + t1]       = f2tf(c[i][j][0] + bz0);
                base[(size_t)(nl + 1) * TT + t1] = f2tf(c[i][j][1] + bz1);
                base[(size_t)nl * TT + t2]       = f2tf(c[i][j][2] + bz0);
                base[(size_t)(nl + 1) * TT + t2] = f2tf(c[i][j][3] + bz1);
            }
        }
    }
}

// ---------------------------------------------------------------------------
// Fused attention: S = lq@K^T, p = mask ? exp(s) : 0 (no max shift — scores
// are bounded small, softmax is shift-invariant), O = p@V, out = O / rowsum.
// grid (11, 64): x = l-tile (128, guarded at 1344), y = b*16+h.
// ---------------------------------------------------------------------------
__global__ __launch_bounds__(256)
void attn_fused(const float* __restrict__ latq, float* __restrict__ out)
{
    extern __shared__ float sm[];
    float* lq_s = sm + LQ_OFF;
    float* Ks   = sm + KS_OFF;
    float* Vs   = sm + VS_OFF;
    float* Ps   = sm + PS_OFF;
    float* rsum = sm + RSUM_OFF;

    const int m0 = blockIdx.x * BM;
    const int bz = blockIdx.y;
    const int b  = bz >> 4, h = bz & 15;
    const int tid = threadIdx.x;
    const int warp = tid >> 5, lane = tid & 31;
    const int wm = warp >> 1, wn = warp & 1;
    const int g = lane >> 2, tig = lane & 3;

    const float* __restrict__ A  = latq + (size_t)h * (LL * DH);
    const float* __restrict__ Kg = g_K  + (size_t)bz * TT * DH;
    const float* __restrict__ Vg = g_Vt + (size_t)bz * DH * TT;
    const uint32_t* __restrict__ Mp = g_Mp + (size_t)b * LL * 32;

    const uint32_t ks_base = (uint32_t)__cvta_generic_to_shared(Ks);
    const uint32_t vs_base = (uint32_t)__cvta_generic_to_shared(Vs);

    // stage lq (x0.25, tf32)
    #pragma unroll
    for (int jj = 0; jj < 8; jj++) {
        const int idx = tid + jj * 256;
        const int row = idx >> 4, f4 = idx & 15;
        float4 v = {0.f, 0.f, 0.f, 0.f};
        if (m0 + row < LL) {
            v = *(const float4*)&A[(size_t)(m0 + row) * DH + f4 * 4];
            v.x *= 0.25f; v.y *= 0.25f; v.z *= 0.25f; v.w *= 0.25f;
        }
        float* d = lq_s + row * FSTR + f4 * 4;
        d[0] = f2tf(v.x); d[1] = f2tf(v.y); d[2] = f2tf(v.z); d[3] = f2tf(v.w);
    }

    float co[2][4][4] = {};
    float srow[2][2] = {};
    __syncthreads();

    for (int tile = 0; tile < TT / 64; tile++) {
        const int t0 = tile * 64;
        // stage K tile [t][d] and V tile [d][t] via cp.async (pre-rounded tf32)
        #pragma unroll
        for (int jj = 0; jj < 4; jj++) {
            const int idx = tid + jj * 256;
            const int row = idx >> 4, f4 = idx & 15;
            const uint32_t doff = (uint32_t)(row * FSTR + f4 * 4) * 4u;
            asm volatile("cp.async.cg.shared.global [%0], [%1], 16;"
                         :: "r"(ks_base + doff), "l"(Kg + (size_t)(t0 + row) * DH + f4 * 4));
            asm volatile("cp.async.cg.shared.global [%0], [%1], 16;"
                         :: "r"(vs_base + doff), "l"(Vg + (size_t)row * TT + t0 + f4 * 4));
        }
        asm volatile("cp.async.commit_group;");
        asm volatile("cp.async.wait_group 0;" ::: "memory");
        __syncthreads();

        // S = lq @ K^T
        float cs[2][4][4] = {};
        compute_mma<FSTR, 8>(lq_s, Ks, cs, wm, wn, g, tig);

        // mask words
        uint32_t mw[2][2];
        #pragma unroll
        for (int i = 0; i < 2; i++) {
            const int lA = m0 + wm * 32 + i * 16 + g;
            const int lB = lA + 8;
            mw[i][0] = (lA < LL) ? Mp[(size_t)lA * 32 + tile * 2 + wn] : 0u;
            mw[i][1] = (lB < LL) ? Mp[(size_t)lB * 32 + tile * 2 + wn] : 0u;
        }

        // p = mask ? exp(s) : 0 ; accumulate register row sums ; write P
        #pragma unroll
        for (int i = 0; i < 2; i++) {
            #pragma unroll
            for (int half = 0; half < 2; half++) {
                const int r = wm * 32 + i * 16 + g + half * 8;
                const uint32_t w32 = mw[i][half];
                const int k = half * 2;
                float sl = 0.f;
                #pragma unroll
                for (int j = 0; j < 4; j++) {
                    const int b0 = j * 8 + tig * 2;
                    const float p0 = ((w32 >> b0) & 1)       ? __expf(cs[i][j][k])     : 0.f;
                    const float p1 = ((w32 >> (b0 + 1)) & 1) ? __expf(cs[i][j][k + 1]) : 0.f;
                    sl += p0 + p1;
                    float2 pv = { f2tf(p0), f2tf(p1) };
                    *(float2*)(Ps + r * FSTR + wn * 32 + b0) = pv;
                }
                srow[i][half] += sl;
            }
        }
        __syncthreads();

        // O += P @ V
        compute_mma<FSTR, 8>(Ps, Vs, co, wm, wn, g, tig);
        __syncthreads();
    }

    // final row-sum reduction: tig shfl, then combine the two wn halves via smem
    #pragma unroll
    for (int i = 0; i < 2; i++) {
        #pragma unroll
        for (int half = 0; half < 2; half++) {
            const int r = wm * 32 + i * 16 + g + half * 8;
            float s = srow[i][half];
            s += __shfl_xor_sync(0xffffffffu, s, 1);
            s += __shfl_xor_sync(0xffffffffu, s, 2);
            if (tig == 0) rsum[r * 2 + wn] = s;
        }
    }
    __syncthreads();

    // epilogue: out[b, l, h*64 + d] = O / rowsum  (0 if fully masked)
    #pragma unroll
    for (int i = 0; i < 2; i++) {
        const int rA = wm * 32 + i * 16 + g, rB = rA + 8;
        const int lA = m0 + rA, lB = m0 + rB;
        const float dA = rsum[rA * 2] + rsum[rA * 2 + 1];
        const float dB = rsum[rB * 2] + rsum[rB * 2 + 1];
        const float invA = dA > 0.f ? __frcp_rn(dA) : 0.f;
        const float invB = dB > 0.f ? __frcp_rn(dB) : 0.f;
        #pragma unroll
        for (int j = 0; j < 4; j++) {
            const int nl = wn * 32 + j * 8 + tig * 2;
            if (lA < LL) {
                float2 v0 = { co[i][j][0] * invA, co[i][j][1] * invA };
                *(float2*)(out + ((size_t)b * LL + lA) * DEMB + h * DH + nl) = v0;
            }
            if (lB < LL) {
                float2 v1 = { co[i][j][2] * invB, co[i][j][3] * invB };
                *(float2*)(out + ((size_t)b * LL + lB) * DEMB + h * DH + nl) = v1;
            }
        }
    }
}

// ---------------------------------------------------------------------------
extern "C" void kernel_launch(void* const* d_in, const int* in_sizes, int n_in,
                              void* d_out, int out_size)
{
    const float* x    = (const float*)d_in[0];
    const int*   msk  = (const int*)d_in[1];
    const float* latq = (const float*)d_in[2];
    const float* wk   = (const float*)d_in[3];
    const float* bk   = (const float*)d_in[4];
    const float* wv   = (const float*)d_in[5];
    const float* bv   = (const float*)d_in[6];
    float*       out  = (float*)d_out;

    cudaFuncSetAttribute(proj_kernel, cudaFuncAttributeMaxDynamicSharedMemorySize, SMEMB);
    cudaFuncSetAttribute(attn_fused,  cudaFuncAttributeMaxDynamicSharedMemorySize, SMEM_ATT_B);

    pack_mask<<<BB * LL / 8, 256>>>(msk);
    proj_kernel<<<dim3(32, 16, 2), 256, SMEMB>>>(x, wk, bk, wv, bv);
    attn_fused <<<dim3(11, 64),    256, SMEM_ATT_B>>>(latq, out);
}